// round 14
// baseline (speedup 1.0000x reference)
// LocallyConnected2d forward (B=16, C=32, O=32, HW=64x64, 3x3, pad=1).
// Target sm_100a. One block handles 8 horizontally adjacent output pixels
// with 128 threads (4 warps, each warp covering two pixels with 16 lanes).
// Per-thread accumulator tile: 4 batches x 8 out-channels, packed fp32x2
// across channel pairs (even channel in .lo, odd channel in .hi).
//
// Weight shared-memory layout (per c-pair): row pk = pix*9+k is 64 floats;
// the 16-float group of o-slot og splits into four 16-byte chunks, chunk j
// placed at granule (4*j + og + rot(pk)) mod 16 where
//   rot(pk) = (F0(pk mod 9) + 4*(pk div 9)) mod 8, F0 = {0,1,2,3,4,5,6,7,3},
// with floats inside a granule rotated by 2*((pk div 9) & 1).
// Compute-side LDS.128 hits all 8 granule residues -> single wavefront.
// Staging stores are cc-paired STS.64, at most ~2-way bank conflicted.
//
// This revision keeps the R12 weight pipeline (distance-2 register prefetch)
// and makes the x tile fully shared-memory resident: all 16 c-pairs staged
// once up front, so the steady-state loop stages weights only.
// Dynamic shared memory: 103.5 KB per block, two blocks per SM.

#include <cuda_runtime.h>

typedef unsigned long long uu64;

__device__ __forceinline__ uu64 packed_fma(uu64 a, uu64 b, uu64 c) {
    uu64 d;
    asm("fma.rn.f32x2 %0, %1, %2, %3;" : "=l"(d) : "l"(a), "l"(b), "l"(c));
    return d;
}

#define WB_F 4608
#define XT_F 1080
#define XR_BASE (2 * WB_F)
#define TOTAL_F (2 * WB_F + 16 * XT_F)     // 26496 floats
#define CSTRIDE 36864

// shared-memory float offset of weight element (pk, o, cc)
__device__ __forceinline__ int woffset(int pk, int o, int cc) {
    int g16  = (o & 7) * 2 + cc;
    int base = (g16 & ~3) + (o >> 3);
    int pos  = g16 & 3;
    int p  = (pk * 57) >> 9;               // pk / 9 for pk < 72
    int q  = pk - p * 9;
    int f0 = q - 5 * (q >> 3);             // {0,1,2,3,4,5,6,7,3}
    int rt = (f0 + 4 * p) & 7;
    return pk * 64 + ((base + rt) & 15) * 4 + ((pos + 2 * (p & 1)) & 3);
}

__global__ __launch_bounds__(128, 2)
void lc2d_fwd(const float* __restrict__ xin,
              const float* __restrict__ wgt,
              float* __restrict__ out)
{
    extern __shared__ __align__(16) float sm[];

    const int tid  = threadIdx.x;
    const int lane = tid & 31;
    const int og   = lane & 3;
    const int bg   = (lane >> 2) & 3;
    const int pix  = (tid >> 5) * 2 + (lane >> 4);
    const int swp  = pix & 1;

    const int oh      = blockIdx.y;
    const int ow0     = blockIdx.x << 3;
    const int pixbase = oh * 64 + ow0;

    // weight staging invariants: four cc-pair float4 items + one leftover
    int wbase4[4];
    unsigned woff64[8];
#pragma unroll
    for (int j = 0; j < 4; ++j) {
        int idx = j * 128 + tid;
        int o   = idx >> 4;
        int v4  = idx & 15;
        wbase4[j] = o * (32 * CSTRIDE) + pixbase * 9 + v4 * 4;
        unsigned a = 0, b = 0;
#pragma unroll
        for (int e = 0; e < 4; ++e) {
            int off = woffset(v4 * 4 + e, o, 0);     // cc=1 sits at off+1
            if (e < 2) a |= (unsigned)off << (16 * e);
            else       b |= (unsigned)off << (16 * (e - 2));
        }
        woff64[j * 2] = a; woff64[j * 2 + 1] = b;
    }
    int wlbase;
    unsigned wloff[2];
    {
        int o  = tid >> 2;
        int t2 = tid & 3;
        int cc = t2 & 1;
        int v4 = 16 + (t2 >> 1);
        wlbase = (o * 32 + cc) * CSTRIDE + pixbase * 9 + v4 * 4;
        unsigned a = 0, b = 0;
#pragma unroll
        for (int e = 0; e < 4; ++e) {
            int off = woffset(v4 * 4 + e, o, cc);
            if (e < 2) a |= (unsigned)off << (16 * e);
            else       b |= (unsigned)off << (16 * (e - 2));
        }
        wloff[0] = a; wloff[1] = b;
    }

    const int wread = pix * 576;
    const int xread = pix * 36 + bg * 8;

    uu64 acc[4][8];
#pragma unroll
    for (int i = 0; i < 4; ++i)
#pragma unroll
        for (int j = 0; j < 8; ++j) acc[i][j] = 0ull;

    float4 wA[4], wB[4], wL;

#define W_LOADS(CC2)                                                          \
    do {                                                                      \
        int cl = (CC2) * (2 * CSTRIDE);                                       \
        _Pragma("unroll")                                                     \
        for (int j = 0; j < 4; ++j) {                                         \
            wA[j] = *reinterpret_cast<const float4*>(wgt + wbase4[j] + cl);   \
            wB[j] = *reinterpret_cast<const float4*>(wgt + wbase4[j] + cl     \
                                                     + CSTRIDE);              \
        }                                                                     \
        wL = *reinterpret_cast<const float4*>(wgt + wlbase + cl);             \
    } while (0)

#define W_STAGE(BUF)                                                          \
    do {                                                                      \
        float* wd = sm + (BUF) * WB_F;                                        \
        _Pragma("unroll")                                                     \
        for (int j = 0; j < 4; ++j) {                                         \
            const float* a = reinterpret_cast<const float*>(&wA[j]);          \
            const float* b = reinterpret_cast<const float*>(&wB[j]);          \
            _Pragma("unroll")                                                 \
            for (int e = 0; e < 4; ++e) {                                     \
                unsigned off = (woff64[j*2 + (e>>1)] >> (16*(e&1))) & 0xffffu;\
                *reinterpret_cast<float2*>(wd + off) =                        \
                    make_float2(a[e], b[e]);                                  \
            }                                                                 \
        }                                                                     \
        {                                                                     \
            const float* l = reinterpret_cast<const float*>(&wL);             \
            wd[wloff[0] & 0xffffu] = l[0];                                    \
            wd[wloff[0] >> 16]     = l[1];                                    \
            wd[wloff[1] & 0xffffu] = l[2];                                    \
            wd[wloff[1] >> 16]     = l[3];                                    \
        }                                                                     \
    } while (0)

    // prologue A: kick off weight loads for the first c-pair
    W_LOADS(0);

    // prologue B: stage the whole x tile (16 c-pairs) into shared memory
    {
        int xg[8], xo[8];
#pragma unroll
        for (int s = 0; s < 8; ++s) {
            int i = tid + s * 128;
            xg[s] = -1; xo[s] = -1;
            if (i < 960) {
                int col = i % 10;
                int r   = i / 10;
                int row = r % 3;
                int qb  = r / 3;
                int b   = qb >> 1;
                int cc  = qb & 1;
                xo[s] = (row * 10 + col) * 36 + b * 2 + cc;
                int ih = oh - 1 + row;
                int iw = ow0 - 1 + col;
                if ((unsigned)ih < 64u && (unsigned)iw < 64u)
                    xg[s] = (b * 32 + cc) * 4096 + ih * 64 + iw;
            }
        }
        for (int cc2 = 0; cc2 < 16; ++cc2) {
            float* xd = sm + XR_BASE + cc2 * XT_F;
            const int cx = cc2 * 8192;
            float v[8];
#pragma unroll
            for (int s = 0; s < 8; ++s)
                if (xo[s] >= 0)
                    v[s] = (xg[s] >= 0) ? __ldg(xin + xg[s] + cx) : 0.f;
#pragma unroll
            for (int s = 0; s < 8; ++s)
                if (xo[s] >= 0) xd[xo[s]] = v[s];
        }
    }

    // prologue C: stage weights buffer 0, prefetch c-pair 1
    W_STAGE(0);
    W_LOADS(1);

    // steady state: weight-only double-buffered pipeline, x read in place
    for (int cc2 = 0; cc2 < 16; ++cc2) {
        const int buf = cc2 & 1;
        __syncthreads();
        if (cc2 < 15) W_STAGE(buf ^ 1);
        if (cc2 < 14) W_LOADS(cc2 + 2);

        const float* wp = sm + buf * WB_F + wread;
        const float* xp = sm + XR_BASE + cc2 * XT_F + xread;
#pragma unroll
        for (int k = 0; k < 9; ++k) {
            const int f0k = (k < 8) ? k : 3;
            const float* xb = xp + ((k / 3) * 10 + (k % 3)) * 36;
            ulonglong2 xlo = *reinterpret_cast<const ulonglong2*>(xb);
            ulonglong2 xhi = *reinterpret_cast<const ulonglong2*>(xb + 4);
            uu64 xv[4] = {xlo.x, xlo.y, xhi.x, xhi.y};

            const float* wkb = wp + k * 64;
            const int t = og + ((f0k + 4 * pix) & 7);
            {
                ulonglong2 wa = *reinterpret_cast<const ulonglong2*>(wkb + ((t    ) & 15) * 4);
                ulonglong2 wc = *reinterpret_cast<const ulonglong2*>(wkb + ((t + 4) & 15) * 4);
                uu64 wv[4] = {wa.x, wa.y, wc.x, wc.y};
#pragma unroll
                for (int bi = 0; bi < 4; ++bi)
#pragma unroll
                    for (int oi = 0; oi < 4; ++oi)
                        acc[bi][oi] = packed_fma(xv[bi], wv[oi], acc[bi][oi]);
            }
            {
                ulonglong2 wa = *reinterpret_cast<const ulonglong2*>(wkb + ((t +  8) & 15) * 4);
                ulonglong2 wc = *reinterpret_cast<const ulonglong2*>(wkb + ((t + 12) & 15) * 4);
                uu64 wv[4] = {wa.x, wa.y, wc.x, wc.y};
#pragma unroll
                for (int bi = 0; bi < 4; ++bi)
#pragma unroll
                    for (int oi = 0; oi < 4; ++oi)
                        acc[bi][oi + 4] = packed_fma(xv[bi], wv[oi], acc[bi][oi + 4]);
            }
        }
    }

    // epilogue: channel-pair reduce, rotation-swap undo, smem transpose, STG
    __syncthreads();
#pragma unroll
    for (int bi = 0; bi < 4; ++bi)
#pragma unroll
        for (int oi = 0; oi < 8; ++oi) {
            union { uu64 u; float2 f; } cv;
            cv.u = acc[bi][oi];
            int bo = (bg * 4 + bi) * 32 + og * 8 + (oi ^ swp);
            sm[bo * 10 + pix] = cv.f.x + cv.f.y;
        }
    __syncthreads();
#pragma unroll
    for (int rr = 0; rr < 4; ++rr) {
        int r = tid + rr * 128;
        const float* sp = sm + r * 10;
        float4 lo = make_float4(sp[0], sp[1], sp[2], sp[3]);
        float4 hi = make_float4(sp[4], sp[5], sp[6], sp[7]);
        float* op = out + (size_t)r * 4096 + pixbase;
        *reinterpret_cast<float4*>(op)     = lo;
        *reinterpret_cast<float4*>(op + 4) = hi;
    }
#undef W_LOADS
#undef W_STAGE
}

extern "C" void kernel_launch(void* const* d_in, const int* in_sizes, int n_in,
                              void* d_out, int out_size) {
    const float* x = (const float*)d_in[0];   // [16,32,64,64] float32
    const float* w = (const float*)d_in[1];   // [32,32,64,64,9] float32
    float* y = (float*)d_out;                 // [16,32,64,64] float32
    cudaFuncSetAttribute(lc2d_fwd,
                         cudaFuncAttributeMaxDynamicSharedMemorySize,
                         TOTAL_F * 4);
    dim3 grid(8, 64);
    lc2d_fwd<<<grid, 128, TOTAL_F * 4>>>(x, w, y);
}